// round 1
// baseline (speedup 1.0000x reference)
#include <cuda_runtime.h>
#include <cstdint>

#define NDIM   8
#define NPAIR  28
#define NH     128
#define DIN    6
#define TILE_B 64
#define THREADS 256
#define LDH    132   // padded leading dim for h tile (conflict-free column reads)

// shared memory layout (floats)
//   sh_h   : TILE_B * LDH      = 8448
//   sh_W   : NH * NH           = 16384
//   sh_x   : TILE_B * NDIM     = 512
//   sh_w1  : DIN * NH          = 768
//   sh_b   : NH                = 128
//   sh_wo  : NH                = 128
#define SMEM_FLOATS (TILE_B*LDH + NH*NH + TILE_B*NDIM + DIN*NH + NH + NH)
#define SMEM_BYTES  (SMEM_FLOATS * 4)

__device__ __forceinline__ float softplus_f(float v) {
    // softplus(x) = max(x,0) + log(1 + exp(-|x|)); fast-math intrinsics, ~1e-6 rel err
    return fmaxf(v, 0.0f) + __logf(1.0f + __expf(-fabsf(v)));
}

__global__ void __launch_bounds__(THREADS, 2)
pairmlp_kernel(const float* __restrict__ x,
               const float* __restrict__ W1,
               const float* __restrict__ b1,
               const float* __restrict__ Wh,
               const float* __restrict__ bh,
               const float* __restrict__ Wout,
               const float* __restrict__ bout,
               const int*   __restrict__ rel_idx,
               const int*   __restrict__ i_idx,
               const int*   __restrict__ j_idx,
               float*       __restrict__ out)
{
    extern __shared__ float sm[];
    float* sh_h  = sm;                          // [TILE_B][LDH]
    float* sh_W  = sh_h  + TILE_B * LDH;        // [NH][NH] row-major (k, c)
    float* sh_x  = sh_W  + NH * NH;             // [TILE_B][NDIM]
    float* sh_w1 = sh_x  + TILE_B * NDIM;       // [DIN][NH]
    float* sh_b  = sh_w1 + DIN * NH;            // [NH]
    float* sh_wo = sh_b  + NH;                  // [NH]

    const int p   = blockIdx.y;
    const int b0  = blockIdx.x * TILE_B;
    const int tid = threadIdx.x;
    const int tx  = tid & 31;       // column group: cols 4*tx .. 4*tx+3
    const int ty  = tid >> 5;       // row group:    rows 8*ty .. 8*ty+7
    const int colbase = tx * 4;
    const int rowbase = ty * 8;

    // ---- prologue loads ----
    {   // x tile: 64x8 = 512 floats = 128 float4
        const float4* xg = (const float4*)(x + (size_t)b0 * NDIM);
        float4* xs = (float4*)sh_x;
        if (tid < (TILE_B * NDIM) / 4) xs[tid] = xg[tid];
    }
    {   // W1[p]: 6*128 = 768 floats = 192 float4
        const float4* g = (const float4*)(W1 + (size_t)p * DIN * NH);
        float4* s = (float4*)sh_w1;
        if (tid < (DIN * NH) / 4) s[tid] = g[tid];
    }
    if (tid < NH) sh_b[tid]  = b1[p * NH + tid];
    if (tid < NH) sh_wo[tid] = Wout[p * NH + tid];

    int rel[DIN];
    #pragma unroll
    for (int d = 0; d < DIN; d++) rel[d] = rel_idx[p * DIN + d];

    __syncthreads();

    float acc[8][4];

    // ---- layer 0: [64 x 6] @ [6 x 128] + b1, softplus ----
    #pragma unroll
    for (int j = 0; j < 4; j++) {
        float bb = sh_b[colbase + j];
        #pragma unroll
        for (int i = 0; i < 8; i++) acc[i][j] = bb;
    }
    #pragma unroll
    for (int d = 0; d < DIN; d++) {
        float w0 = sh_w1[d * NH + colbase + 0];
        float w1v= sh_w1[d * NH + colbase + 1];
        float w2 = sh_w1[d * NH + colbase + 2];
        float w3 = sh_w1[d * NH + colbase + 3];
        #pragma unroll
        for (int i = 0; i < 8; i++) {
            float a = sh_x[(rowbase + i) * NDIM + rel[d]];   // warp-broadcast
            acc[i][0] = fmaf(a, w0,  acc[i][0]);
            acc[i][1] = fmaf(a, w1v, acc[i][1]);
            acc[i][2] = fmaf(a, w2,  acc[i][2]);
            acc[i][3] = fmaf(a, w3,  acc[i][3]);
        }
    }
    #pragma unroll
    for (int i = 0; i < 8; i++) {
        float4 v;
        v.x = softplus_f(acc[i][0]);
        v.y = softplus_f(acc[i][1]);
        v.z = softplus_f(acc[i][2]);
        v.w = softplus_f(acc[i][3]);
        *(float4*)&sh_h[(rowbase + i) * LDH + colbase] = v;
    }

    // ---- hidden layers l = 0,1: [64 x 128] @ [128 x 128] + bh, softplus ----
    for (int l = 0; l < 2; l++) {
        __syncthreads();   // h stores visible; previous sh_W reads done
        {   // stage Wh[l][p] (16384 floats = 4096 float4), coalesced
            const float4* g = (const float4*)(Wh + ((size_t)l * NPAIR + p) * NH * NH);
            float4* s = (float4*)sh_W;
            #pragma unroll
            for (int it = 0; it < (NH * NH / 4) / THREADS; it++)
                s[tid + it * THREADS] = g[tid + it * THREADS];
        }
        if (tid < NH) sh_b[tid] = bh[((size_t)l * NPAIR + p) * NH + tid];
        __syncthreads();

        #pragma unroll
        for (int j = 0; j < 4; j++) {
            float bb = sh_b[colbase + j];
            #pragma unroll
            for (int i = 0; i < 8; i++) acc[i][j] = bb;
        }

        #pragma unroll 4
        for (int k = 0; k < NH; k += 4) {
            // 4 weight rows, vectorized (conflict-free: warp covers a full 512B row)
            float4 w0 = *(const float4*)&sh_W[(k + 0) * NH + colbase];
            float4 w1v= *(const float4*)&sh_W[(k + 1) * NH + colbase];
            float4 w2 = *(const float4*)&sh_W[(k + 2) * NH + colbase];
            float4 w3 = *(const float4*)&sh_W[(k + 3) * NH + colbase];
            #pragma unroll
            for (int i = 0; i < 8; i++) {
                // broadcast load of 4 consecutive h values for this row
                float4 a = *(const float4*)&sh_h[(rowbase + i) * LDH + k];
                acc[i][0] = fmaf(a.x, w0.x,  acc[i][0]);
                acc[i][1] = fmaf(a.x, w0.y,  acc[i][1]);
                acc[i][2] = fmaf(a.x, w0.z,  acc[i][2]);
                acc[i][3] = fmaf(a.x, w0.w,  acc[i][3]);
                acc[i][0] = fmaf(a.y, w1v.x, acc[i][0]);
                acc[i][1] = fmaf(a.y, w1v.y, acc[i][1]);
                acc[i][2] = fmaf(a.y, w1v.z, acc[i][2]);
                acc[i][3] = fmaf(a.y, w1v.w, acc[i][3]);
                acc[i][0] = fmaf(a.z, w2.x,  acc[i][0]);
                acc[i][1] = fmaf(a.z, w2.y,  acc[i][1]);
                acc[i][2] = fmaf(a.z, w2.z,  acc[i][2]);
                acc[i][3] = fmaf(a.z, w2.w,  acc[i][3]);
                acc[i][0] = fmaf(a.w, w3.x,  acc[i][0]);
                acc[i][1] = fmaf(a.w, w3.y,  acc[i][1]);
                acc[i][2] = fmaf(a.w, w3.z,  acc[i][2]);
                acc[i][3] = fmaf(a.w, w3.w,  acc[i][3]);
            }
        }

        __syncthreads();   // all sh_h reads done before overwrite
        #pragma unroll
        for (int i = 0; i < 8; i++) {
            float4 v;
            v.x = softplus_f(acc[i][0]);
            v.y = softplus_f(acc[i][1]);
            v.z = softplus_f(acc[i][2]);
            v.w = softplus_f(acc[i][3]);
            *(float4*)&sh_h[(rowbase + i) * LDH + colbase] = v;
        }
    }

    __syncthreads();

    // ---- output layer: vals[r] = h[r,:] . Wout + bout ----
    // 4 threads per row; thread (row, q) sums columns c = q + 4*c'  (conflict-free)
    const int row = tid >> 2;
    const int q   = tid & 3;
    float s = 0.0f;
    #pragma unroll
    for (int c = 0; c < 32; c++) {
        int cc = q + 4 * c;
        s += sh_h[row * LDH + cc] * sh_wo[cc];
    }
    s += __shfl_xor_sync(0xffffffffu, s, 1);
    s += __shfl_xor_sync(0xffffffffu, s, 2);
    if (q == 0) {
        float val = s + bout[p];
        int b  = b0 + row;
        int ii = i_idx[p];
        int jj = j_idx[p];
        out[(size_t)b * (NDIM * NDIM) + ii * NDIM + jj] =  val;
        out[(size_t)b * (NDIM * NDIM) + jj * NDIM + ii] = -val;
    }
}

// Zero the diagonal (all off-diagonal entries are written by pair CTAs)
__global__ void zero_diag_kernel(float* __restrict__ out, int batch)
{
    int t = blockIdx.x * blockDim.x + threadIdx.x;
    if (t < batch * NDIM) {
        int b = t >> 3;
        int d = t & 7;
        out[(size_t)b * (NDIM * NDIM) + d * (NDIM + 1)] = 0.0f;
    }
}

extern "C" void kernel_launch(void* const* d_in, const int* in_sizes, int n_in,
                              void* d_out, int out_size)
{
    const float* x    = (const float*)d_in[0];
    const float* W1   = (const float*)d_in[1];
    const float* b1   = (const float*)d_in[2];
    const float* Wh   = (const float*)d_in[3];
    const float* bh   = (const float*)d_in[4];
    const float* Wout = (const float*)d_in[5];
    const float* bout = (const float*)d_in[6];
    const int*   rel  = (const int*)d_in[7];
    const int*   iidx = (const int*)d_in[8];
    const int*   jidx = (const int*)d_in[9];
    float* out = (float*)d_out;

    const int batch = in_sizes[0] / NDIM;

    cudaFuncSetAttribute(pairmlp_kernel,
                         cudaFuncAttributeMaxDynamicSharedMemorySize, SMEM_BYTES);

    zero_diag_kernel<<<(batch * NDIM + 255) / 256, 256>>>(out, batch);

    dim3 grid(batch / TILE_B, NPAIR);
    pairmlp_kernel<<<grid, THREADS, SMEM_BYTES>>>(
        x, W1, b1, Wh, bh, Wout, bout, rel, iidx, jidx, out);
}